// round 5
// baseline (speedup 1.0000x reference)
#include <cuda_runtime.h>
#include <cuda_bf16.h>
#include <cstdint>

#define D       256
#define KNBR    16
#define LN_EPS  1e-5f
#define TILE_M  64
#define NCHUNK  8          // K chunks of 32 for W streaming
#define KCH     32
#define AP      264        // A row pitch (bf16 elems): 528 B, %128=16 -> conflict-free
#define BP      40         // B row pitch (bf16 elems):  80 B, %128=80 -> conflict-free

// W transposed + split (persistent, tiny: 256 KB total)
__device__ __nv_bfloat16 wt_hi[D * D];   // [n][k]
__device__ __nv_bfloat16 wt_lo[D * D];

// ---------------- smem layout (bytes) ---------------------------------------
#define A_SPLIT   (TILE_M * AP * 2)                  // 33792
#define OFF_A_HI  0
#define OFF_A_LO  (A_SPLIT)
#define B_SPLIT   (D * BP * 2)                       // 20480
#define B_STAGE   (2 * B_SPLIT)                      // 40960
#define OFF_B     (2 * A_SPLIT)                      // 67584
#define OFF_PAR   (OFF_B + 2 * B_STAGE)              // 149504
#define OFF_REDS  (OFF_PAR + 3 * D * 4)              // 152576
#define OFF_RED2  (OFF_REDS + TILE_M * 4 * 4)        // 153600
#define OFF_SW    (OFF_RED2 + TILE_M * 4 * 4)        // 154624
#define OFF_SNB   (OFF_SW + TILE_M * KNBR * 4)       // 158720
#define SMEM_TOTAL (OFF_SNB + TILE_M * KNBR * 4)     // 162816

// ---------------- helpers ---------------------------------------------------
__device__ __forceinline__ uint32_t smem_u32(const void* p) {
    uint32_t a;
    asm("{ .reg .u64 t; cvta.to.shared.u64 t, %1; cvt.u32.u64 %0, t; }"
        : "=r"(a) : "l"(p));
    return a;
}
__device__ __forceinline__ void cp16(uint32_t dst, const void* src) {
    asm volatile("cp.async.cg.shared.global [%0], [%1], 16;" :: "r"(dst), "l"(src));
}
__device__ __forceinline__ void ldm4(uint32_t* r, uint32_t addr) {
    asm volatile("ldmatrix.sync.aligned.m8n8.x4.shared.b16 {%0,%1,%2,%3}, [%4];"
                 : "=r"(r[0]), "=r"(r[1]), "=r"(r[2]), "=r"(r[3]) : "r"(addr));
}
__device__ __forceinline__ void mma16816(float* c, const uint32_t* a,
                                         uint32_t b0, uint32_t b1) {
    asm volatile("mma.sync.aligned.m16n8k16.row.col.f32.bf16.bf16.f32 "
                 "{%0,%1,%2,%3}, {%4,%5,%6,%7}, {%8,%9}, {%0,%1,%2,%3};"
                 : "+f"(c[0]), "+f"(c[1]), "+f"(c[2]), "+f"(c[3])
                 : "r"(a[0]), "r"(a[1]), "r"(a[2]), "r"(a[3]), "r"(b0), "r"(b1));
}

// ---------------------------------------------------------------------------
// Kernel 0: split + transpose W via smem tiles (coalesced both directions)
// grid (8,8), block (32,8)
// ---------------------------------------------------------------------------
__global__ void prep_w_kernel(const float* __restrict__ W)
{
    __shared__ float s[32][33];
    const int n0 = blockIdx.x * 32, k0 = blockIdx.y * 32;
    const int tx = threadIdx.x, ty = threadIdx.y;
#pragma unroll
    for (int i = 0; i < 4; i++)
        s[ty + 8 * i][tx] = W[(size_t)(k0 + ty + 8 * i) * D + n0 + tx];
    __syncthreads();
#pragma unroll
    for (int i = 0; i < 4; i++) {
        const int nl = ty + 8 * i;
        const float v = s[tx][nl];
        const __nv_bfloat16 h = __float2bfloat16(v);
        const __nv_bfloat16 l = __float2bfloat16(v - __bfloat162float(h));
        wt_hi[(size_t)(n0 + nl) * D + k0 + tx] = h;
        wt_lo[(size_t)(n0 + nl) * D + k0 + tx] = l;
    }
}

// ---------------------------------------------------------------------------
// Fused kernel: register gather (64 nodes) -> smem bf16 hi/lo A tile ->
// split-bf16 mma.sync GEMM with W double-buffered via cp.async -> fused LN.
// 256 threads: gather thread = (row = tid>>2, quarter q = tid&3).
// MMA warps: wm = wid&1 (rows), wn = wid>>1 (64-col group).
// ---------------------------------------------------------------------------
__global__ __launch_bounds__(256, 1) void fused_kernel(
    const float* __restrict__ feats,
    const int* __restrict__ nbrs,
    const float* __restrict__ iw,
    const float* __restrict__ bias,
    const float* __restrict__ gamma,
    const float* __restrict__ beta,
    float* __restrict__ out, int n)
{
    extern __shared__ char smem[];
    const uint32_t sb = smem_u32(smem);
    const int tid  = threadIdx.x;
    const int lane = tid & 31;
    const int wid  = tid >> 5;
    const int m0   = blockIdx.x * TILE_M;

    // ---- prefetch W chunks 0 and 1 (overlaps with the gather phase) -------
    auto load_b_chunk = [&](int st, int c) {
        const uint32_t base = sb + OFF_B + (uint32_t)st * B_STAGE;
#pragma unroll
        for (int i = 0; i < 8; i++) {
            const int idx = tid + i * 256;          // 0..2047
            const int split = idx >> 10;
            const int r  = (idx >> 2) & 255;
            const int g  = idx & 3;
            const __nv_bfloat16* src = (split ? wt_lo : wt_hi)
                                     + (size_t)r * D + c * KCH + g * 8;
            cp16(base + (uint32_t)split * B_SPLIT + (uint32_t)r * (BP * 2)
                      + (uint32_t)g * 16, src);
        }
        asm volatile("cp.async.commit_group;");
    };
    load_b_chunk(0, 0);
    load_b_chunk(1, 1);

    // ---- stage params + per-node weights/indices --------------------------
    {
        float* p = (float*)(smem + OFF_PAR);
        for (int i = tid; i < D; i += 256) {
            p[i]         = bias[i];
            p[D + i]     = gamma[i];
            p[2 * D + i] = beta[i];
        }
        float* sw  = (float*)(smem + OFF_SW);
        int*   snb = (int*)(smem + OFF_SNB);
#pragma unroll
        for (int i = 0; i < 4; i++) {
            const int idx  = tid + i * 256;        // 0..1023
            const int node = m0 + (idx >> 4);
            const int k    = idx & 15;
            float w = 0.f; int ix = 0;
            if (node < n) {
                w  = iw[(size_t)node * KNBR + k];
                ix = nbrs[(size_t)node * KNBR + k];
                ix = ix < 0 ? 0 : (ix >= n ? n - 1 : ix);
            }
            sw[idx]  = w;
            snb[idx] = ix;
        }
    }
    __syncthreads();

    // ---- register gather: row r, cols [q*64, q*64+64) ---------------------
    {
        const int r = tid >> 2;          // 0..63
        const int q = tid & 3;           // 0..3
        const int node = m0 + r;
        float4 acc[16];
#pragma unroll
        for (int c = 0; c < 16; c++) acc[c] = make_float4(0.f, 0.f, 0.f, 0.f);

        if (node < n) {
            const float* sw  = (const float*)(smem + OFF_SW) + r * KNBR;
            const int*   snb = (const int*)(smem + OFF_SNB) + r * KNBR;
            float wsum = 0.f;
#pragma unroll
            for (int k = 0; k < KNBR; k++) wsum += sw[k];
            const bool zero = (wsum == 0.f);
            const float inv = zero ? 0.f : 1.0f / wsum;

            const float4* f4 = (const float4*)feats;
#pragma unroll
            for (int k = 0; k < KNBR; k++) {
                const float w = zero ? (1.0f / KNBR) : sw[k] * inv;
                const float4* fp = f4 + (size_t)snb[k] * (D / 4) + q * 16;
#pragma unroll
                for (int c = 0; c < 16; c++) {
                    const float4 f = fp[c];
                    acc[c].x = fmaf(w, f.x, acc[c].x);
                    acc[c].y = fmaf(w, f.y, acc[c].y);
                    acc[c].z = fmaf(w, f.z, acc[c].z);
                    acc[c].w = fmaf(w, f.w, acc[c].w);
                }
            }
        }
        // convert to bf16 hi/lo, store into smem A tile
        char* aHi = smem + OFF_A_HI + r * (AP * 2);
        char* aLo = smem + OFF_A_LO + r * (AP * 2);
#pragma unroll
        for (int c = 0; c < 16; c++) {
            const float v[4] = {acc[c].x, acc[c].y, acc[c].z, acc[c].w};
            uint32_t ph[2], pl[2];
#pragma unroll
            for (int i = 0; i < 2; i++) {
                const __nv_bfloat16 h0 = __float2bfloat16(v[2 * i]);
                const __nv_bfloat16 h1 = __float2bfloat16(v[2 * i + 1]);
                const __nv_bfloat16 l0 = __float2bfloat16(v[2 * i]     - __bfloat162float(h0));
                const __nv_bfloat16 l1 = __float2bfloat16(v[2 * i + 1] - __bfloat162float(h1));
                ph[i] = ((uint32_t)__bfloat16_as_ushort(h1) << 16) | __bfloat16_as_ushort(h0);
                pl[i] = ((uint32_t)__bfloat16_as_ushort(l1) << 16) | __bfloat16_as_ushort(l0);
            }
            const int cb = (q * 64 + c * 4) * 2;
            *(uint2*)(aHi + cb) = make_uint2(ph[0], ph[1]);
            *(uint2*)(aLo + cb) = make_uint2(pl[0], pl[1]);
        }
    }

    // ---- GEMM: 8 chunks of K=32, W double-buffered ------------------------
    const int wm = wid & 1;
    const int wn = wid >> 1;
    float accm[2][8][4];
#pragma unroll
    for (int t = 0; t < 2; t++)
#pragma unroll
        for (int j = 0; j < 8; j++)
#pragma unroll
            for (int p = 0; p < 4; p++) accm[t][j][p] = 0.f;

    const uint32_t a_lane = (uint32_t)(lane & 15) * (AP * 2) + (uint32_t)(lane >> 4) * 16;
    const uint32_t b_lane = (uint32_t)((lane & 7) + ((lane >> 4) << 3)) * (BP * 2)
                          + (uint32_t)((lane >> 3) & 1) * 16;

#pragma unroll
    for (int c = 0; c < NCHUNK; c++) {
        if (c < NCHUNK - 1) asm volatile("cp.async.wait_group 1;");
        else                asm volatile("cp.async.wait_group 0;");
        __syncthreads();

        const uint32_t bbase = sb + OFF_B + (uint32_t)(c & 1) * B_STAGE;
#pragma unroll
        for (int ks = 0; ks < 2; ks++) {
            uint32_t ah[2][4], al[2][4], bh[4][4], bl[4][4];
#pragma unroll
            for (int t = 0; t < 2; t++) {
                const uint32_t ao = sb + (uint32_t)(wm * 32 + t * 16) * (AP * 2)
                                  + (uint32_t)(c * 64 + ks * 32) + a_lane;
                ldm4(ah[t], ao + OFF_A_HI);
                ldm4(al[t], ao + OFF_A_LO);
            }
#pragma unroll
            for (int p = 0; p < 4; p++) {
                const uint32_t bo = bbase + (uint32_t)(wn * 64 + p * 16) * (BP * 2)
                                  + (uint32_t)(ks * 32) + b_lane;
                ldm4(bh[p], bo);
                ldm4(bl[p], bo + B_SPLIT);
            }
#pragma unroll
            for (int t = 0; t < 2; t++)
#pragma unroll
                for (int j = 0; j < 8; j++) {
                    const uint32_t h0 = bh[j >> 1][(j & 1) * 2];
                    const uint32_t h1 = bh[j >> 1][(j & 1) * 2 + 1];
                    const uint32_t l0 = bl[j >> 1][(j & 1) * 2];
                    const uint32_t l1 = bl[j >> 1][(j & 1) * 2 + 1];
                    mma16816(accm[t][j], ah[t], h0, h1);
                    mma16816(accm[t][j], ah[t], l0, l1);
                    mma16816(accm[t][j], al[t], h0, h1);
                }
        }
        __syncthreads();
        if (c + 2 < NCHUNK) load_b_chunk(c & 1, c + 2);
    }

    // ---- fused LayerNorm epilogue -----------------------------------------
    const float* bias_s = (const float*)(smem + OFF_PAR);
    const float* gam_s  = bias_s + D;
    const float* bet_s  = bias_s + 2 * D;

    float s[4]  = {0.f, 0.f, 0.f, 0.f};
    float s2[4] = {0.f, 0.f, 0.f, 0.f};
#pragma unroll
    for (int t = 0; t < 2; t++)
#pragma unroll
        for (int j = 0; j < 8; j++)
#pragma unroll
            for (int p = 0; p < 4; p++) {
                const int col = wn * 64 + j * 8 + (lane & 3) * 2 + (p & 1);
                const float v = accm[t][j][p] + bias_s[col];
                accm[t][j][p] = v;
                const int slot = t * 2 + (p >> 1);
                s[slot] += v;
                s2[slot] = fmaf(v, v, s2[slot]);
            }
#pragma unroll
    for (int slot = 0; slot < 4; slot++) {
        s[slot]  += __shfl_xor_sync(0xffffffffu, s[slot], 1);
        s2[slot] += __shfl_xor_sync(0xffffffffu, s2[slot], 1);
        s[slot]  += __shfl_xor_sync(0xffffffffu, s[slot], 2);
        s2[slot] += __shfl_xor_sync(0xffffffffu, s2[slot], 2);
    }
    float* redS  = (float*)(smem + OFF_REDS);
    float* redS2 = (float*)(smem + OFF_RED2);
    if ((lane & 3) == 0) {
#pragma unroll
        for (int slot = 0; slot < 4; slot++) {
            const int row = wm * 32 + (slot >> 1) * 16 + (slot & 1) * 8 + (lane >> 2);
            redS[row * 4 + wn]  = s[slot];
            redS2[row * 4 + wn] = s2[slot];
        }
    }
    __syncthreads();

#pragma unroll
    for (int slot = 0; slot < 4; slot++) {
        const int row = wm * 32 + (slot >> 1) * 16 + (slot & 1) * 8 + (lane >> 2);
        const float S = redS[row * 4 + 0] + redS[row * 4 + 1]
                      + redS[row * 4 + 2] + redS[row * 4 + 3];
        const float Q = redS2[row * 4 + 0] + redS2[row * 4 + 1]
                      + redS2[row * 4 + 2] + redS2[row * 4 + 3];
        const float mean = S * (1.0f / D);
        const float var  = fmaxf(Q * (1.0f / D) - mean * mean, 0.f);
        const float rstd = rsqrtf(var + LN_EPS);
        const int gr = m0 + row;
        if (gr < n) {
            const int t = slot >> 1, h = slot & 1;
#pragma unroll
            for (int j = 0; j < 8; j++) {
                const int col = wn * 64 + j * 8 + (lane & 3) * 2;
                float2 o;
                o.x = (accm[t][j][h * 2 + 0] - mean) * rstd * gam_s[col]     + bet_s[col];
                o.y = (accm[t][j][h * 2 + 1] - mean) * rstd * gam_s[col + 1] + bet_s[col + 1];
                *(float2*)&out[(size_t)gr * D + col] = o;
            }
        }
    }
}

// ---------------------------------------------------------------------------
extern "C" void kernel_launch(void* const* d_in, const int* in_sizes, int n_in,
                              void* d_out, int out_size)
{
    const float* feats = (const float*)d_in[0];
    const int*   nbrs  = (const int*)d_in[1];
    const float* iw    = (const float*)d_in[2];
    const float* Wm    = (const float*)d_in[3];
    const float* bias  = (const float*)d_in[4];
    const float* gam   = (const float*)d_in[5];
    const float* bet   = (const float*)d_in[6];
    float*       out   = (float*)d_out;

    const int n = in_sizes[0] / D;   // 50000

    cudaFuncSetAttribute(fused_kernel,
                         cudaFuncAttributeMaxDynamicSharedMemorySize, SMEM_TOTAL);

    prep_w_kernel<<<dim3(8, 8), dim3(32, 8)>>>(Wm);
    fused_kernel<<<(n + TILE_M - 1) / TILE_M, 256, SMEM_TOTAL>>>(
        feats, nbrs, iw, bias, gam, bet, out, n);
}

// round 6
// speedup vs baseline: 2.1549x; 2.1549x over previous
#include <cuda_runtime.h>
#include <cuda_bf16.h>
#include <cuda_fp16.h>
#include <cstdint>

#define D       256
#define KNBR    16
#define MAXN    50000
#define LN_EPS  1e-5f
#define TILE_M  64
#define KCH     64
#define ROWP    72      // padded row pitch in bf16 elems (144 B) -> conflict-free ldmatrix

// ---------------- scratch (static device arrays; no allocations) ------------
__device__ __half         feat16[(size_t)MAXN * D];   // fp16 copy of features (25.6 MB)
__device__ __nv_bfloat16  g_hi[(size_t)MAXN * D];
__device__ __nv_bfloat16  g_lo[(size_t)MAXN * D];
__device__ __nv_bfloat16  wt_hi[D * D];   // [n][k] = W[k][n] hi part
__device__ __nv_bfloat16  wt_lo[D * D];   // [n][k] lo part

// ---------------- smem layout for GEMM (bytes) ------------------------------
#define A_SPLIT_BYTES (TILE_M * ROWP * 2)          //  9216
#define B_SPLIT_BYTES (D * ROWP * 2)               // 36864
#define OFF_A_HI 0
#define OFF_A_LO (A_SPLIT_BYTES)
#define OFF_B_HI (2 * A_SPLIT_BYTES)
#define OFF_B_LO (2 * A_SPLIT_BYTES + B_SPLIT_BYTES)
#define STAGE    (2 * A_SPLIT_BYTES + 2 * B_SPLIT_BYTES)   // 92160
#define OFF_PAR  (2 * STAGE)                       // 184320 : bias|gamma|beta
#define OFF_REDS (OFF_PAR + 3 * D * 4)             // 187392
#define OFF_RED2 (OFF_REDS + TILE_M * 4 * 4)       // 188416
#define SMEM_TOTAL (OFF_RED2 + TILE_M * 4 * 4)     // 189440

// ---------------- helpers ---------------------------------------------------
__device__ __forceinline__ uint32_t smem_u32(const void* p) {
    uint32_t a;
    asm("{ .reg .u64 t; cvta.to.shared.u64 t, %1; cvt.u32.u64 %0, t; }"
        : "=r"(a) : "l"(p));
    return a;
}
__device__ __forceinline__ void cp16(uint32_t dst, const void* src, bool valid) {
    const int sz = valid ? 16 : 0;
    asm volatile("cp.async.cg.shared.global [%0], [%1], 16, %2;"
                 :: "r"(dst), "l"(src), "r"(sz));
}
__device__ __forceinline__ void ldm4(uint32_t* r, uint32_t addr) {
    asm volatile("ldmatrix.sync.aligned.m8n8.x4.shared.b16 {%0,%1,%2,%3}, [%4];"
                 : "=r"(r[0]), "=r"(r[1]), "=r"(r[2]), "=r"(r[3]) : "r"(addr));
}
__device__ __forceinline__ void mma16816(float* c, const uint32_t* a,
                                         uint32_t b0, uint32_t b1) {
    asm volatile("mma.sync.aligned.m16n8k16.row.col.f32.bf16.bf16.f32 "
                 "{%0,%1,%2,%3}, {%4,%5,%6,%7}, {%8,%9}, {%0,%1,%2,%3};"
                 : "+f"(c[0]), "+f"(c[1]), "+f"(c[2]), "+f"(c[3])
                 : "r"(a[0]), "r"(a[1]), "r"(a[2]), "r"(a[3]), "r"(b0), "r"(b1));
}

// ---------------------------------------------------------------------------
// Kernel 0a: split + transpose W via smem tiles (coalesced both directions)
// ---------------------------------------------------------------------------
__global__ void prep_w_kernel(const float* __restrict__ W)
{
    __shared__ float s[32][33];
    const int n0 = blockIdx.x * 32, k0 = blockIdx.y * 32;
    const int tx = threadIdx.x, ty = threadIdx.y;
#pragma unroll
    for (int i = 0; i < 4; i++)
        s[ty + 8 * i][tx] = W[(size_t)(k0 + ty + 8 * i) * D + n0 + tx];
    __syncthreads();
#pragma unroll
    for (int i = 0; i < 4; i++) {
        const int nl = ty + 8 * i;
        const float v = s[tx][nl];
        const __nv_bfloat16 h = __float2bfloat16(v);
        const __nv_bfloat16 l = __float2bfloat16(v - __bfloat162float(h));
        wt_hi[(size_t)(n0 + nl) * D + k0 + tx] = h;
        wt_lo[(size_t)(n0 + nl) * D + k0 + tx] = l;
    }
}

// ---------------------------------------------------------------------------
// Kernel 0b: features fp32 -> fp16 (one-time pass, halves gather read traffic)
// ---------------------------------------------------------------------------
__global__ __launch_bounds__(256) void feat_half_kernel(
    const float* __restrict__ feats, int total4)
{
    const int i = blockIdx.x * 256 + threadIdx.x;
    if (i >= total4) return;
    const float4 v = ((const float4*)feats)[i];
    const __half2 a = __floats2half2_rn(v.x, v.y);
    const __half2 b = __floats2half2_rn(v.z, v.w);
    uint2 pk;
    pk.x = *(const uint32_t*)&a;
    pk.y = *(const uint32_t*)&b;
    *(uint2*)&feat16[(size_t)i * 4] = pk;
}

// ---------------------------------------------------------------------------
// Kernel A: weighted gather over fp16 features (fp32 accumulate),
// emits bf16 hi/lo split of g.  64 threads per node (4 elems each),
// 4 nodes per 256-thread block.
// ---------------------------------------------------------------------------
__global__ __launch_bounds__(256) void gather_kernel(
    const int* __restrict__ nbrs,
    const float* __restrict__ iw,
    int n)
{
    __shared__ float sw[4][KNBR];
    __shared__ int   snb[4][KNBR];
    const int tid   = threadIdx.x;
    const int local = tid >> 6;
    const int t     = tid & 63;
    const int node  = blockIdx.x * 4 + local;

    if (t < KNBR && node < n) {
        sw[local][t] = iw[(size_t)node * KNBR + t];
        int ix = nbrs[(size_t)node * KNBR + t];
        ix = ix < 0 ? 0 : (ix >= n ? n - 1 : ix);
        snb[local][t] = ix;
    }
    __syncthreads();
    if (node >= n) return;

    float wsum = 0.f;
#pragma unroll
    for (int k = 0; k < KNBR; k++) wsum += sw[local][k];
    float wn[KNBR];
    if (wsum == 0.f) {
#pragma unroll
        for (int k = 0; k < KNBR; k++) wn[k] = 1.0f / KNBR;
    } else {
        const float inv = 1.0f / wsum;
#pragma unroll
        for (int k = 0; k < KNBR; k++) wn[k] = sw[local][k] * inv;
    }

    const uint2* f2 = (const uint2*)feat16;     // 4 halves per load
    float4 acc = make_float4(0.f, 0.f, 0.f, 0.f);
#pragma unroll
    for (int k = 0; k < KNBR; k++) {
        const uint2 raw = f2[(size_t)snb[local][k] * (D / 4) + t];
        const float2 p0 = __half22float2(*(const __half2*)&raw.x);
        const float2 p1 = __half22float2(*(const __half2*)&raw.y);
        const float w = wn[k];
        acc.x = fmaf(w, p0.x, acc.x);
        acc.y = fmaf(w, p0.y, acc.y);
        acc.z = fmaf(w, p1.x, acc.z);
        acc.w = fmaf(w, p1.y, acc.w);
    }

    float v[4] = {acc.x, acc.y, acc.z, acc.w};
    uint32_t ph[2], pl[2];
#pragma unroll
    for (int i = 0; i < 2; i++) {
        __nv_bfloat16 h0 = __float2bfloat16(v[2 * i]);
        __nv_bfloat16 h1 = __float2bfloat16(v[2 * i + 1]);
        __nv_bfloat16 l0 = __float2bfloat16(v[2 * i]     - __bfloat162float(h0));
        __nv_bfloat16 l1 = __float2bfloat16(v[2 * i + 1] - __bfloat162float(h1));
        ph[i] = ((uint32_t)__bfloat16_as_ushort(h1) << 16) | __bfloat16_as_ushort(h0);
        pl[i] = ((uint32_t)__bfloat16_as_ushort(l1) << 16) | __bfloat16_as_ushort(l0);
    }
    const size_t e = (size_t)node * D + t * 4;
    *(uint2*)&g_hi[e] = make_uint2(ph[0], ph[1]);
    *(uint2*)&g_lo[e] = make_uint2(pl[0], pl[1]);
}

// ---------------------------------------------------------------------------
// Kernel B: split-bf16 GEMM via mma.sync (m16n8k16), 3-pass,
// tile 64x256, K in 4 chunks of 64, cp.async double-buffering, fused LN.
// (byte-identical logic to the validated R4 kernel)
// ---------------------------------------------------------------------------
__global__ __launch_bounds__(256, 1) void gemm_ln_mma_kernel(
    const float* __restrict__ bias,
    const float* __restrict__ gamma,
    const float* __restrict__ beta,
    float* __restrict__ out, int n)
{
    extern __shared__ char smem[];
    const uint32_t sb = smem_u32(smem);
    const int tid  = threadIdx.x;
    const int lane = tid & 31;
    const int wid  = tid >> 5;
    const int wm   = wid & 1;
    const int wn   = wid >> 1;
    const int m0   = blockIdx.x * TILE_M;

    {
        float* p = (float*)(smem + OFF_PAR);
        for (int i = tid; i < D; i += 256) {
            p[i]         = bias[i];
            p[D + i]     = gamma[i];
            p[2 * D + i] = beta[i];
        }
    }

    float acc[2][8][4];
#pragma unroll
    for (int t = 0; t < 2; t++)
#pragma unroll
        for (int j = 0; j < 8; j++)
#pragma unroll
            for (int q = 0; q < 4; q++) acc[t][j][q] = 0.f;

    const uint32_t a_lane = (uint32_t)(lane & 15) * (ROWP * 2) + (uint32_t)(lane >> 4) * 16;
    const uint32_t b_lane = (uint32_t)((lane & 7) + ((lane >> 4) << 3)) * (ROWP * 2)
                          + (uint32_t)((lane >> 3) & 1) * 16;

    auto load_stage = [&](int st, int c) {
        const int k0 = c * KCH;
        const uint32_t base = sb + st * STAGE;
#pragma unroll
        for (int i = 0; i < 4; i++) {
            const int idx = tid + i * 256;
            const int split = idx >> 9;
            const int r  = (idx >> 3) & 63;
            const int c8 = idx & 7;
            const int grow = m0 + r;
            const bool valid = grow < n;
            const int gr = valid ? grow : 0;
            const __nv_bfloat16* src = (split ? g_lo : g_hi) + (size_t)gr * D + k0 + c8 * 8;
            const uint32_t dst = base + (split ? OFF_A_LO : OFF_A_HI)
                               + (uint32_t)r * (ROWP * 2) + (uint32_t)c8 * 16;
            cp16(dst, src, valid);
        }
#pragma unroll
        for (int i = 0; i < 16; i++) {
            const int idx = tid + i * 256;
            const int split = idx >> 11;
            const int r  = (idx >> 3) & 255;
            const int c8 = idx & 7;
            const __nv_bfloat16* src = (split ? wt_lo : wt_hi) + (size_t)r * D + k0 + c8 * 8;
            const uint32_t dst = base + (split ? OFF_B_LO : OFF_B_HI)
                               + (uint32_t)r * (ROWP * 2) + (uint32_t)c8 * 16;
            cp16(dst, src, true);
        }
        asm volatile("cp.async.commit_group;");
    };

    load_stage(0, 0);

#pragma unroll
    for (int c = 0; c < 4; c++) {
        if (c < 3) {
            load_stage((c + 1) & 1, c + 1);
            asm volatile("cp.async.wait_group 1;");
        } else {
            asm volatile("cp.async.wait_group 0;");
        }
        __syncthreads();

        const uint32_t base = sb + (uint32_t)(c & 1) * STAGE;
#pragma unroll
        for (int ks = 0; ks < 4; ks++) {
            uint32_t ah[2][4], al[2][4], bh[4][4], bl[4][4];
#pragma unroll
            for (int t = 0; t < 2; t++) {
                const uint32_t ao = base + (uint32_t)(wm * 32 + t * 16) * (ROWP * 2)
                                  + (uint32_t)ks * 32 + a_lane;
                ldm4(ah[t], ao + OFF_A_HI);
                ldm4(al[t], ao + OFF_A_LO);
            }
#pragma unroll
            for (int p = 0; p < 4; p++) {
                const uint32_t bo = base + (uint32_t)(wn * 64 + p * 16) * (ROWP * 2)
                                  + (uint32_t)ks * 32 + b_lane;
                ldm4(bh[p], bo + OFF_B_HI);
                ldm4(bl[p], bo + OFF_B_LO);
            }
#pragma unroll
            for (int t = 0; t < 2; t++)
#pragma unroll
                for (int j = 0; j < 8; j++) {
                    const uint32_t h0 = bh[j >> 1][(j & 1) * 2];
                    const uint32_t h1 = bh[j >> 1][(j & 1) * 2 + 1];
                    const uint32_t l0 = bl[j >> 1][(j & 1) * 2];
                    const uint32_t l1 = bl[j >> 1][(j & 1) * 2 + 1];
                    mma16816(acc[t][j], ah[t], h0, h1);
                    mma16816(acc[t][j], ah[t], l0, l1);
                    mma16816(acc[t][j], al[t], h0, h1);
                }
        }
        __syncthreads();
    }

    const float* bias_s = (const float*)(smem + OFF_PAR);
    const float* gam_s  = bias_s + D;
    const float* bet_s  = bias_s + 2 * D;

    float s[4]  = {0.f, 0.f, 0.f, 0.f};
    float s2[4] = {0.f, 0.f, 0.f, 0.f};
#pragma unroll
    for (int t = 0; t < 2; t++)
#pragma unroll
        for (int j = 0; j < 8; j++)
#pragma unroll
            for (int q = 0; q < 4; q++) {
                const int col = wn * 64 + j * 8 + (lane & 3) * 2 + (q & 1);
                const float v = acc[t][j][q] + bias_s[col];
                acc[t][j][q] = v;
                const int slot = t * 2 + (q >> 1);
                s[slot] += v;
                s2[slot] = fmaf(v, v, s2[slot]);
            }
#pragma unroll
    for (int slot = 0; slot < 4; slot++) {
        s[slot]  += __shfl_xor_sync(0xffffffffu, s[slot], 1);
        s2[slot] += __shfl_xor_sync(0xffffffffu, s2[slot], 1);
        s[slot]  += __shfl_xor_sync(0xffffffffu, s[slot], 2);
        s2[slot] += __shfl_xor_sync(0xffffffffu, s2[slot], 2);
    }
    float* redS  = (float*)(smem + OFF_REDS);
    float* redS2 = (float*)(smem + OFF_RED2);
    if ((lane & 3) == 0) {
#pragma unroll
        for (int slot = 0; slot < 4; slot++) {
            const int row = wm * 32 + (slot >> 1) * 16 + (slot & 1) * 8 + (lane >> 2);
            redS[row * 4 + wn]  = s[slot];
            redS2[row * 4 + wn] = s2[slot];
        }
    }
    __syncthreads();

#pragma unroll
    for (int slot = 0; slot < 4; slot++) {
        const int row = wm * 32 + (slot >> 1) * 16 + (slot & 1) * 8 + (lane >> 2);
        const float S  = redS[row * 4 + 0] + redS[row * 4 + 1]
                       + redS[row * 4 + 2] + redS[row * 4 + 3];
        const float Q  = redS2[row * 4 + 0] + redS2[row * 4 + 1]
                       + redS2[row * 4 + 2] + redS2[row * 4 + 3];
        const float mean = S * (1.0f / D);
        const float var  = fmaxf(Q * (1.0f / D) - mean * mean, 0.f);
        const float rstd = rsqrtf(var + LN_EPS);
        const int gr = m0 + row;
        if (gr < n) {
            const int t = slot >> 1, h = slot & 1;
#pragma unroll
            for (int j = 0; j < 8; j++) {
                const int col = wn * 64 + j * 8 + (lane & 3) * 2;
                float2 o;
                o.x = (acc[t][j][h * 2 + 0] - mean) * rstd * gam_s[col]     + bet_s[col];
                o.y = (acc[t][j][h * 2 + 1] - mean) * rstd * gam_s[col + 1] + bet_s[col + 1];
                *(float2*)&out[(size_t)gr * D + col] = o;
            }
        }
    }
}

// ---------------------------------------------------------------------------
extern "C" void kernel_launch(void* const* d_in, const int* in_sizes, int n_in,
                              void* d_out, int out_size)
{
    const float* feats = (const float*)d_in[0];
    const int*   nbrs  = (const int*)d_in[1];
    const float* iw    = (const float*)d_in[2];
    const float* Wm    = (const float*)d_in[3];
    const float* bias  = (const float*)d_in[4];
    const float* gam   = (const float*)d_in[5];
    const float* bet   = (const float*)d_in[6];
    float*       out   = (float*)d_out;

    const int n = in_sizes[0] / D;   // 50000

    cudaFuncSetAttribute(gemm_ln_mma_kernel,
                         cudaFuncAttributeMaxDynamicSharedMemorySize, SMEM_TOTAL);

    prep_w_kernel<<<dim3(8, 8), dim3(32, 8)>>>(Wm);
    const int total4 = n * (D / 4);
    feat_half_kernel<<<(total4 + 255) / 256, 256>>>(feats, total4);
    gather_kernel<<<(n + 3) / 4, 256>>>(nbrs, iw, n);
    gemm_ln_mma_kernel<<<(n + TILE_M - 1) / TILE_M, 256, SMEM_TOTAL>>>(bias, gam, bet, out, n);
}

// round 7
// speedup vs baseline: 2.4990x; 1.1597x over previous
#include <cuda_runtime.h>
#include <cuda_fp16.h>
#include <cstdint>

#define D       256
#define KNBR    16
#define MAXN    50000
#define LN_EPS  1e-5f
#define TILE_M  64
#define KCH     64
#define ROWP    72      // padded row pitch in fp16 elems (144 B) -> conflict-free ldmatrix

// ---------------- scratch (static device arrays; no allocations) ------------
__device__ __half feat16[(size_t)MAXN * D];   // fp16 features (25.6 MB)
__device__ __half g_half[(size_t)MAXN * D];   // aggregated g, fp16 (25.6 MB)
__device__ __half wt_hi[D * D];               // [n][k] = W[k][n] fp16 hi
__device__ __half wt_lo[D * D];               // [n][k] fp16 lo (residual, ~2^-22)

// ---------------- smem layout for GEMM (bytes) ------------------------------
#define A_BYTES       (TILE_M * ROWP * 2)          //  9216
#define B_SPLIT_BYTES (D * ROWP * 2)               // 36864
#define OFF_A    0
#define OFF_B_HI (A_BYTES)
#define OFF_B_LO (A_BYTES + B_SPLIT_BYTES)
#define STAGE    (A_BYTES + 2 * B_SPLIT_BYTES)     // 82944
#define OFF_PAR  (2 * STAGE)                       // 165888 : bias|gamma|beta
#define OFF_REDS (OFF_PAR + 3 * D * 4)             // 168960
#define OFF_RED2 (OFF_REDS + TILE_M * 4 * 4)       // 169984
#define SMEM_TOTAL (OFF_RED2 + TILE_M * 4 * 4)     // 171008

// ---------------- helpers ---------------------------------------------------
__device__ __forceinline__ uint32_t smem_u32(const void* p) {
    uint32_t a;
    asm("{ .reg .u64 t; cvta.to.shared.u64 t, %1; cvt.u32.u64 %0, t; }"
        : "=r"(a) : "l"(p));
    return a;
}
__device__ __forceinline__ void cp16(uint32_t dst, const void* src, bool valid) {
    const int sz = valid ? 16 : 0;
    asm volatile("cp.async.cg.shared.global [%0], [%1], 16, %2;"
                 :: "r"(dst), "l"(src), "r"(sz));
}
__device__ __forceinline__ void ldm4(uint32_t* r, uint32_t addr) {
    asm volatile("ldmatrix.sync.aligned.m8n8.x4.shared.b16 {%0,%1,%2,%3}, [%4];"
                 : "=r"(r[0]), "=r"(r[1]), "=r"(r[2]), "=r"(r[3]) : "r"(addr));
}
__device__ __forceinline__ void mma_f16(float* c, const uint32_t* a,
                                        uint32_t b0, uint32_t b1) {
    asm volatile("mma.sync.aligned.m16n8k16.row.col.f32.f16.f16.f32 "
                 "{%0,%1,%2,%3}, {%4,%5,%6,%7}, {%8,%9}, {%0,%1,%2,%3};"
                 : "+f"(c[0]), "+f"(c[1]), "+f"(c[2]), "+f"(c[3])
                 : "r"(a[0]), "r"(a[1]), "r"(a[2]), "r"(a[3]), "r"(b0), "r"(b1));
}

// ---------------------------------------------------------------------------
// Kernel 0a: split + transpose W -> fp16 hi/lo, via smem tile (coalesced)
// ---------------------------------------------------------------------------
__global__ void prep_w_kernel(const float* __restrict__ W)
{
    __shared__ float s[32][33];
    const int n0 = blockIdx.x * 32, k0 = blockIdx.y * 32;
    const int tx = threadIdx.x, ty = threadIdx.y;
#pragma unroll
    for (int i = 0; i < 4; i++)
        s[ty + 8 * i][tx] = W[(size_t)(k0 + ty + 8 * i) * D + n0 + tx];
    __syncthreads();
#pragma unroll
    for (int i = 0; i < 4; i++) {
        const int nl = ty + 8 * i;
        const float v = s[tx][nl];
        const __half h = __float2half_rn(v);
        const __half l = __float2half_rn(v - __half2float(h));
        wt_hi[(size_t)(n0 + nl) * D + k0 + tx] = h;
        wt_lo[(size_t)(n0 + nl) * D + k0 + tx] = l;
    }
}

// ---------------------------------------------------------------------------
// Kernel 0b: features fp32 -> fp16 (one-time; halves gather read traffic)
// ---------------------------------------------------------------------------
__global__ __launch_bounds__(256) void feat_half_kernel(
    const float* __restrict__ feats, int total4)
{
    const int i = blockIdx.x * 256 + threadIdx.x;
    if (i >= total4) return;
    const float4 v = ((const float4*)feats)[i];
    const __half2 a = __floats2half2_rn(v.x, v.y);
    const __half2 b = __floats2half2_rn(v.z, v.w);
    uint2 pk;
    pk.x = *(const uint32_t*)&a;
    pk.y = *(const uint32_t*)&b;
    *(uint2*)&feat16[(size_t)i * 4] = pk;
}

// ---------------------------------------------------------------------------
// Kernel A: weighted gather over fp16 features (fp32 accumulate) -> g fp16.
// 64 threads per node (4 elems each), 4 nodes per 256-thread block.
// ---------------------------------------------------------------------------
__global__ __launch_bounds__(256) void gather_kernel(
    const int* __restrict__ nbrs,
    const float* __restrict__ iw,
    int n)
{
    __shared__ float sw[4][KNBR];
    __shared__ int   snb[4][KNBR];
    const int tid   = threadIdx.x;
    const int local = tid >> 6;
    const int t     = tid & 63;
    const int node  = blockIdx.x * 4 + local;

    if (t < KNBR && node < n) {
        sw[local][t] = iw[(size_t)node * KNBR + t];
        int ix = nbrs[(size_t)node * KNBR + t];
        ix = ix < 0 ? 0 : (ix >= n ? n - 1 : ix);
        snb[local][t] = ix;
    }
    __syncthreads();
    if (node >= n) return;

    float wsum = 0.f;
#pragma unroll
    for (int k = 0; k < KNBR; k++) wsum += sw[local][k];
    float wn[KNBR];
    if (wsum == 0.f) {
#pragma unroll
        for (int k = 0; k < KNBR; k++) wn[k] = 1.0f / KNBR;
    } else {
        const float inv = 1.0f / wsum;
#pragma unroll
        for (int k = 0; k < KNBR; k++) wn[k] = sw[local][k] * inv;
    }

    const uint2* f2 = (const uint2*)feat16;
    float4 acc = make_float4(0.f, 0.f, 0.f, 0.f);
#pragma unroll
    for (int k = 0; k < KNBR; k++) {
        const uint2 raw = f2[(size_t)snb[local][k] * (D / 4) + t];
        const float2 p0 = __half22float2(*(const __half2*)&raw.x);
        const float2 p1 = __half22float2(*(const __half2*)&raw.y);
        const float w = wn[k];
        acc.x = fmaf(w, p0.x, acc.x);
        acc.y = fmaf(w, p0.y, acc.y);
        acc.z = fmaf(w, p1.x, acc.z);
        acc.w = fmaf(w, p1.y, acc.w);
    }

    const __half2 h0 = __floats2half2_rn(acc.x, acc.y);
    const __half2 h1 = __floats2half2_rn(acc.z, acc.w);
    uint2 pk;
    pk.x = *(const uint32_t*)&h0;
    pk.y = *(const uint32_t*)&h1;
    *(uint2*)&g_half[(size_t)node * D + t * 4] = pk;
}

// ---------------------------------------------------------------------------
// Kernel B: fp16 GEMM via mma.sync (m16n8k16), 2-pass (A*B_hi + A*B_lo),
// tile 64x256, K in 4 chunks of 64, cp.async double-buffering, fused LN.
// Warp grid: wm = wid&1 (32 rows), wn = wid>>1 (64-col group).
// ---------------------------------------------------------------------------
__global__ __launch_bounds__(256, 1) void gemm_ln_mma_kernel(
    const float* __restrict__ bias,
    const float* __restrict__ gamma,
    const float* __restrict__ beta,
    float* __restrict__ out, int n)
{
    extern __shared__ char smem[];
    const uint32_t sb = smem_u32(smem);
    const int tid  = threadIdx.x;
    const int lane = tid & 31;
    const int wid  = tid >> 5;
    const int wm   = wid & 1;
    const int wn   = wid >> 1;
    const int m0   = blockIdx.x * TILE_M;

    {
        float* p = (float*)(smem + OFF_PAR);
        for (int i = tid; i < D; i += 256) {
            p[i]         = bias[i];
            p[D + i]     = gamma[i];
            p[2 * D + i] = beta[i];
        }
    }

    float acc[2][8][4];
#pragma unroll
    for (int t = 0; t < 2; t++)
#pragma unroll
        for (int j = 0; j < 8; j++)
#pragma unroll
            for (int q = 0; q < 4; q++) acc[t][j][q] = 0.f;

    const uint32_t a_lane = (uint32_t)(lane & 15) * (ROWP * 2) + (uint32_t)(lane >> 4) * 16;
    const uint32_t b_lane = (uint32_t)((lane & 7) + ((lane >> 4) << 3)) * (ROWP * 2)
                          + (uint32_t)((lane >> 3) & 1) * 16;

    auto load_stage = [&](int st, int c) {
        const int k0 = c * KCH;
        const uint32_t base = sb + st * STAGE;
        // A: 64 rows x 8 chunks(16B) = 512 -> 2/thread
#pragma unroll
        for (int i = 0; i < 2; i++) {
            const int idx = tid + i * 256;          // 0..511
            const int r  = idx >> 3;
            const int c8 = idx & 7;
            const int grow = m0 + r;
            const bool valid = grow < n;
            const int gr = valid ? grow : 0;
            const __half* src = g_half + (size_t)gr * D + k0 + c8 * 8;
            cp16(base + OFF_A + (uint32_t)r * (ROWP * 2) + (uint32_t)c8 * 16, src, valid);
        }
        // B: 2 splits x 256 rows x 8 chunks = 4096 -> 16/thread
#pragma unroll
        for (int i = 0; i < 16; i++) {
            const int idx = tid + i * 256;
            const int split = idx >> 11;
            const int r  = (idx >> 3) & 255;
            const int c8 = idx & 7;
            const __half* src = (split ? wt_lo : wt_hi) + (size_t)r * D + k0 + c8 * 8;
            const uint32_t dst = base + (split ? OFF_B_LO : OFF_B_HI)
                               + (uint32_t)r * (ROWP * 2) + (uint32_t)c8 * 16;
            cp16(dst, src, true);
        }
        asm volatile("cp.async.commit_group;");
    };

    load_stage(0, 0);

#pragma unroll
    for (int c = 0; c < 4; c++) {
        if (c < 3) {
            load_stage((c + 1) & 1, c + 1);
            asm volatile("cp.async.wait_group 1;");
        } else {
            asm volatile("cp.async.wait_group 0;");
        }
        __syncthreads();

        const uint32_t base = sb + (uint32_t)(c & 1) * STAGE;
#pragma unroll
        for (int ks = 0; ks < 4; ks++) {
            uint32_t ah[2][4], bh[4][4], bl[4][4];
#pragma unroll
            for (int t = 0; t < 2; t++) {
                const uint32_t ao = base + OFF_A
                                  + (uint32_t)(wm * 32 + t * 16) * (ROWP * 2)
                                  + (uint32_t)ks * 32 + a_lane;
                ldm4(ah[t], ao);
            }
#pragma unroll
            for (int p = 0; p < 4; p++) {
                const uint32_t bo = base + (uint32_t)(wn * 64 + p * 16) * (ROWP * 2)
                                  + (uint32_t)ks * 32 + b_lane;
                ldm4(bh[p], bo + OFF_B_HI);
                ldm4(bl[p], bo + OFF_B_LO);
            }
#pragma unroll
            for (int t = 0; t < 2; t++)
#pragma unroll
                for (int j = 0; j < 8; j++) {
                    const uint32_t h0 = bh[j >> 1][(j & 1) * 2];
                    const uint32_t h1 = bh[j >> 1][(j & 1) * 2 + 1];
                    const uint32_t l0 = bl[j >> 1][(j & 1) * 2];
                    const uint32_t l1 = bl[j >> 1][(j & 1) * 2 + 1];
                    mma_f16(acc[t][j], ah[t], h0, h1);
                    mma_f16(acc[t][j], ah[t], l0, l1);
                }
        }
        __syncthreads();
    }

    // ---------------- fused LayerNorm epilogue -----------------------------
    const float* bias_s = (const float*)(smem + OFF_PAR);
    const float* gam_s  = bias_s + D;
    const float* bet_s  = bias_s + 2 * D;

    float s[4]  = {0.f, 0.f, 0.f, 0.f};
    float s2[4] = {0.f, 0.f, 0.f, 0.f};
#pragma unroll
    for (int t = 0; t < 2; t++)
#pragma unroll
        for (int j = 0; j < 8; j++)
#pragma unroll
            for (int q = 0; q < 4; q++) {
                const int col = wn * 64 + j * 8 + (lane & 3) * 2 + (q & 1);
                const float v = acc[t][j][q] + bias_s[col];
                acc[t][j][q] = v;
                const int slot = t * 2 + (q >> 1);
                s[slot] += v;
                s2[slot] = fmaf(v, v, s2[slot]);
            }
#pragma unroll
    for (int slot = 0; slot < 4; slot++) {
        s[slot]  += __shfl_xor_sync(0xffffffffu, s[slot], 1);
        s2[slot] += __shfl_xor_sync(0xffffffffu, s2[slot], 1);
        s[slot]  += __shfl_xor_sync(0xffffffffu, s[slot], 2);
        s2[slot] += __shfl_xor_sync(0xffffffffu, s2[slot], 2);
    }
    float* redS  = (float*)(smem + OFF_REDS);
    float* redS2 = (float*)(smem + OFF_RED2);
    if ((lane & 3) == 0) {
#pragma unroll
        for (int slot = 0; slot < 4; slot++) {
            const int row = wm * 32 + (slot >> 1) * 16 + (slot & 1) * 8 + (lane >> 2);
            redS[row * 4 + wn]  = s[slot];
            redS2[row * 4 + wn] = s2[slot];
        }
    }
    __syncthreads();

#pragma unroll
    for (int slot = 0; slot < 4; slot++) {
        const int row = wm * 32 + (slot >> 1) * 16 + (slot & 1) * 8 + (lane >> 2);
        const float S  = redS[row * 4 + 0] + redS[row * 4 + 1]
                       + redS[row * 4 + 2] + redS[row * 4 + 3];
        const float Q  = redS2[row * 4 + 0] + redS2[row * 4 + 1]
                       + redS2[row * 4 + 2] + redS2[row * 4 + 3];
        const float mean = S * (1.0f / D);
        const float var  = fmaxf(Q * (1.0f / D) - mean * mean, 0.f);
        const float rstd = rsqrtf(var + LN_EPS);
        const int gr = m0 + row;
        if (gr < n) {
            const int t = slot >> 1, h = slot & 1;
#pragma unroll
            for (int j = 0; j < 8; j++) {
                const int col = wn * 64 + j * 8 + (lane & 3) * 2;
                float2 o;
                o.x = (acc[t][j][h * 2 + 0] - mean) * rstd * gam_s[col]     + bet_s[col];
                o.y = (acc[t][j][h * 2 + 1] - mean) * rstd * gam_s[col + 1] + bet_s[col + 1];
                *(float2*)&out[(size_t)gr * D + col] = o;
            }
        }
    }
}

// ---------------------------------------------------------------------------
extern "C" void kernel_launch(void* const* d_in, const int* in_sizes, int n_in,
                              void* d_out, int out_size)
{
    const float* feats = (const float*)d_in[0];
    const int*   nbrs  = (const int*)d_in[1];
    const float* iw    = (const float*)d_in[2];
    const float* Wm    = (const float*)d_in[3];
    const float* bias  = (const float*)d_in[4];
    const float* gam   = (const float*)d_in[5];
    const float* bet   = (const float*)d_in[6];
    float*       out   = (float*)d_out;

    const int n = in_sizes[0] / D;   // 50000

    cudaFuncSetAttribute(gemm_ln_mma_kernel,
                         cudaFuncAttributeMaxDynamicSharedMemorySize, SMEM_TOTAL);

    prep_w_kernel<<<dim3(8, 8), dim3(32, 8)>>>(Wm);
    const int total4 = n * (D / 4);
    feat_half_kernel<<<(total4 + 255) / 256, 256>>>(feats, total4);
    gather_kernel<<<(n + 3) / 4, 256>>>(nbrs, iw, n);
    gemm_ln_mma_kernel<<<(n + TILE_M - 1) / TILE_M, 256, SMEM_TOTAL>>>(bias, gam, bet, out, n);
}

// round 8
// speedup vs baseline: 3.1073x; 1.2434x over previous
#include <cuda_runtime.h>
#include <cuda_fp16.h>
#include <cstdint>

#define D       256
#define KNBR    16
#define MAXN    50000
#define LN_EPS  1e-5f
#define TILE_M  64
#define KCH     64
#define ROWP    72      // padded row pitch in fp16 elems (144 B) -> conflict-free ldmatrix

// ---------------- scratch (static device arrays; no allocations) ------------
__device__ __half feat16[(size_t)MAXN * D];   // fp16 features (25.6 MB)
__device__ __half g_half[(size_t)MAXN * D];   // aggregated g, fp16 (25.6 MB)
__device__ __half wt16[D * D];                // [n][k] = W[k][n] fp16

// ---------------- smem layout for GEMM (bytes) ------------------------------
#define A_BYTES  (TILE_M * ROWP * 2)               //  9216
#define B_BYTES  (D * ROWP * 2)                    // 36864
#define OFF_A    0
#define OFF_B    (A_BYTES)
#define STAGE    (A_BYTES + B_BYTES)               // 46080
#define OFF_PAR  (2 * STAGE)                       // 92160 : bias|gamma|beta
#define OFF_REDS (OFF_PAR + 3 * D * 4)             // 95232
#define OFF_RED2 (OFF_REDS + TILE_M * 4 * 4)       // 96256
#define SMEM_TOTAL (OFF_RED2 + TILE_M * 4 * 4)     // 97280  -> 2 CTAs/SM

// ---------------- helpers ---------------------------------------------------
__device__ __forceinline__ uint32_t smem_u32(const void* p) {
    uint32_t a;
    asm("{ .reg .u64 t; cvta.to.shared.u64 t, %1; cvt.u32.u64 %0, t; }"
        : "=r"(a) : "l"(p));
    return a;
}
__device__ __forceinline__ void cp16(uint32_t dst, const void* src, bool valid) {
    const int sz = valid ? 16 : 0;
    asm volatile("cp.async.cg.shared.global [%0], [%1], 16, %2;"
                 :: "r"(dst), "l"(src), "r"(sz));
}
__device__ __forceinline__ void ldm4(uint32_t* r, uint32_t addr) {
    asm volatile("ldmatrix.sync.aligned.m8n8.x4.shared.b16 {%0,%1,%2,%3}, [%4];"
                 : "=r"(r[0]), "=r"(r[1]), "=r"(r[2]), "=r"(r[3]) : "r"(addr));
}
__device__ __forceinline__ void mma_f16(float* c, const uint32_t* a,
                                        uint32_t b0, uint32_t b1) {
    asm volatile("mma.sync.aligned.m16n8k16.row.col.f32.f16.f16.f32 "
                 "{%0,%1,%2,%3}, {%4,%5,%6,%7}, {%8,%9}, {%0,%1,%2,%3};"
                 : "+f"(c[0]), "+f"(c[1]), "+f"(c[2]), "+f"(c[3])
                 : "r"(a[0]), "r"(a[1]), "r"(a[2]), "r"(a[3]), "r"(b0), "r"(b1));
}

// ---------------------------------------------------------------------------
// Kernel 0a: transpose W -> fp16 [n][k], via smem tile (coalesced)
// ---------------------------------------------------------------------------
__global__ void prep_w_kernel(const float* __restrict__ W)
{
    __shared__ float s[32][33];
    const int n0 = blockIdx.x * 32, k0 = blockIdx.y * 32;
    const int tx = threadIdx.x, ty = threadIdx.y;
#pragma unroll
    for (int i = 0; i < 4; i++)
        s[ty + 8 * i][tx] = W[(size_t)(k0 + ty + 8 * i) * D + n0 + tx];
    __syncthreads();
#pragma unroll
    for (int i = 0; i < 4; i++) {
        const int nl = ty + 8 * i;
        wt16[(size_t)(n0 + nl) * D + k0 + tx] = __float2half_rn(s[tx][nl]);
    }
}

// ---------------------------------------------------------------------------
// Kernel 0b: features fp32 -> fp16 (one-time; halves gather read traffic)
// ---------------------------------------------------------------------------
__global__ __launch_bounds__(256) void feat_half_kernel(
    const float* __restrict__ feats, int total4)
{
    const int i = blockIdx.x * 256 + threadIdx.x;
    if (i >= total4) return;
    const float4 v = ((const float4*)feats)[i];
    const __half2 a = __floats2half2_rn(v.x, v.y);
    const __half2 b = __floats2half2_rn(v.z, v.w);
    uint2 pk;
    pk.x = *(const uint32_t*)&a;
    pk.y = *(const uint32_t*)&b;
    *(uint2*)&feat16[(size_t)i * 4] = pk;
}

// ---------------------------------------------------------------------------
// Kernel A: weighted gather over fp16 features (fp32 accumulate) -> g fp16.
// 64 threads per node (4 elems each), 4 nodes per 256-thread block.
// ---------------------------------------------------------------------------
__global__ __launch_bounds__(256) void gather_kernel(
    const int* __restrict__ nbrs,
    const float* __restrict__ iw,
    int n)
{
    __shared__ float sw[4][KNBR];
    __shared__ int   snb[4][KNBR];
    const int tid   = threadIdx.x;
    const int local = tid >> 6;
    const int t     = tid & 63;
    const int node  = blockIdx.x * 4 + local;

    if (t < KNBR && node < n) {
        sw[local][t] = iw[(size_t)node * KNBR + t];
        int ix = nbrs[(size_t)node * KNBR + t];
        ix = ix < 0 ? 0 : (ix >= n ? n - 1 : ix);
        snb[local][t] = ix;
    }
    __syncthreads();
    if (node >= n) return;

    float wsum = 0.f;
#pragma unroll
    for (int k = 0; k < KNBR; k++) wsum += sw[local][k];
    float wn[KNBR];
    if (wsum == 0.f) {
#pragma unroll
        for (int k = 0; k < KNBR; k++) wn[k] = 1.0f / KNBR;
    } else {
        const float inv = 1.0f / wsum;
#pragma unroll
        for (int k = 0; k < KNBR; k++) wn[k] = sw[local][k] * inv;
    }

    const uint2* f2 = (const uint2*)feat16;
    float4 acc = make_float4(0.f, 0.f, 0.f, 0.f);
#pragma unroll
    for (int k = 0; k < KNBR; k++) {
        const uint2 raw = f2[(size_t)snb[local][k] * (D / 4) + t];
        const float2 p0 = __half22float2(*(const __half2*)&raw.x);
        const float2 p1 = __half22float2(*(const __half2*)&raw.y);
        const float w = wn[k];
        acc.x = fmaf(w, p0.x, acc.x);
        acc.y = fmaf(w, p0.y, acc.y);
        acc.z = fmaf(w, p1.x, acc.z);
        acc.w = fmaf(w, p1.y, acc.w);
    }

    const __half2 h0 = __floats2half2_rn(acc.x, acc.y);
    const __half2 h1 = __floats2half2_rn(acc.z, acc.w);
    uint2 pk;
    pk.x = *(const uint32_t*)&h0;
    pk.y = *(const uint32_t*)&h1;
    *(uint2*)&g_half[(size_t)node * D + t * 4] = pk;
}

// ---------------------------------------------------------------------------
// Kernel B: fp16 GEMM via mma.sync (m16n8k16), single pass,
// tile 64x256, K in 4 chunks of 64, cp.async double-buffering, fused LN.
// 2 CTAs/SM (97 KB smem, regs capped at 128).
// ---------------------------------------------------------------------------
__global__ __launch_bounds__(256, 2) void gemm_ln_mma_kernel(
    const float* __restrict__ bias,
    const float* __restrict__ gamma,
    const float* __restrict__ beta,
    float* __restrict__ out, int n)
{
    extern __shared__ char smem[];
    const uint32_t sb = smem_u32(smem);
    const int tid  = threadIdx.x;
    const int lane = tid & 31;
    const int wid  = tid >> 5;
    const int wm   = wid & 1;
    const int wn   = wid >> 1;
    const int m0   = blockIdx.x * TILE_M;

    {
        float* p = (float*)(smem + OFF_PAR);
        for (int i = tid; i < D; i += 256) {
            p[i]         = bias[i];
            p[D + i]     = gamma[i];
            p[2 * D + i] = beta[i];
        }
    }

    float acc[2][8][4];
#pragma unroll
    for (int t = 0; t < 2; t++)
#pragma unroll
        for (int j = 0; j < 8; j++)
#pragma unroll
            for (int q = 0; q < 4; q++) acc[t][j][q] = 0.f;

    const uint32_t a_lane = (uint32_t)(lane & 15) * (ROWP * 2) + (uint32_t)(lane >> 4) * 16;
    const uint32_t b_lane = (uint32_t)((lane & 7) + ((lane >> 4) << 3)) * (ROWP * 2)
                          + (uint32_t)((lane >> 3) & 1) * 16;

    auto load_stage = [&](int st, int c) {
        const int k0 = c * KCH;
        const uint32_t base = sb + st * STAGE;
        // A: 64 rows x 8 chunks(16B) = 512 -> 2/thread
#pragma unroll
        for (int i = 0; i < 2; i++) {
            const int idx = tid + i * 256;
            const int r  = idx >> 3;
            const int c8 = idx & 7;
            const int grow = m0 + r;
            const bool valid = grow < n;
            const int gr = valid ? grow : 0;
            const __half* src = g_half + (size_t)gr * D + k0 + c8 * 8;
            cp16(base + OFF_A + (uint32_t)r * (ROWP * 2) + (uint32_t)c8 * 16, src, valid);
        }
        // B: 256 rows x 8 chunks = 2048 -> 8/thread
#pragma unroll
        for (int i = 0; i < 8; i++) {
            const int idx = tid + i * 256;
            const int r  = idx >> 3;
            const int c8 = idx & 7;
            const __half* src = wt16 + (size_t)r * D + k0 + c8 * 8;
            cp16(base + OFF_B + (uint32_t)r * (ROWP * 2) + (uint32_t)c8 * 16, src, true);
        }
        asm volatile("cp.async.commit_group;");
    };

    load_stage(0, 0);

#pragma unroll
    for (int c = 0; c < 4; c++) {
        if (c < 3) {
            load_stage((c + 1) & 1, c + 1);
            asm volatile("cp.async.wait_group 1;");
        } else {
            asm volatile("cp.async.wait_group 0;");
        }
        __syncthreads();

        const uint32_t base = sb + (uint32_t)(c & 1) * STAGE;
#pragma unroll
        for (int ks = 0; ks < 4; ks++) {
            uint32_t ah[2][4], bh[4][4];
#pragma unroll
            for (int t = 0; t < 2; t++) {
                const uint32_t ao = base + OFF_A
                                  + (uint32_t)(wm * 32 + t * 16) * (ROWP * 2)
                                  + (uint32_t)ks * 32 + a_lane;
                ldm4(ah[t], ao);
            }
#pragma unroll
            for (int p = 0; p < 4; p++) {
                const uint32_t bo = base + OFF_B
                                  + (uint32_t)(wn * 64 + p * 16) * (ROWP * 2)
                                  + (uint32_t)ks * 32 + b_lane;
                ldm4(bh[p], bo);
            }
#pragma unroll
            for (int t = 0; t < 2; t++)
#pragma unroll
                for (int j = 0; j < 8; j++)
                    mma_f16(acc[t][j], ah[t],
                            bh[j >> 1][(j & 1) * 2], bh[j >> 1][(j & 1) * 2 + 1]);
        }
        __syncthreads();
    }

    // ---------------- fused LayerNorm epilogue -----------------------------
    const float* bias_s = (const float*)(smem + OFF_PAR);
    const float* gam_s  = bias_s + D;
    const float* bet_s  = bias_s + 2 * D;

    float s[4]  = {0.f, 0.f, 0.f, 0.f};
    float s2[4] = {0.f, 0.f, 0.f, 0.f};
#pragma unroll
    for (int t = 0; t < 2; t++)
#pragma unroll
        for (int j = 0; j < 8; j++)
#pragma unroll
            for (int q = 0; q < 4; q++) {
                const int col = wn * 64 + j * 8 + (lane & 3) * 2 + (q & 1);
                const float v = acc[t][j][q] + bias_s[col];
                acc[t][j][q] = v;
                const int slot = t * 2 + (q >> 1);
                s[slot] += v;
                s2[slot] = fmaf(v, v, s2[slot]);
            }
#pragma unroll
    for (int slot = 0; slot < 4; slot++) {
        s[slot]  += __shfl_xor_sync(0xffffffffu, s[slot], 1);
        s2[slot] += __shfl_xor_sync(0xffffffffu, s2[slot], 1);
        s[slot]  += __shfl_xor_sync(0xffffffffu, s[slot], 2);
        s2[slot] += __shfl_xor_sync(0xffffffffu, s2[slot], 2);
    }
    float* redS  = (float*)(smem + OFF_REDS);
    float* redS2 = (float*)(smem + OFF_RED2);
    if ((lane & 3) == 0) {
#pragma unroll
        for (int slot = 0; slot < 4; slot++) {
            const int row = wm * 32 + (slot >> 1) * 16 + (slot & 1) * 8 + (lane >> 2);
            redS[row * 4 + wn]  = s[slot];
            redS2[row * 4 + wn] = s2[slot];
        }
    }
    __syncthreads();

#pragma unroll
    for (int slot = 0; slot < 4; slot++) {
        const int row = wm * 32 + (slot >> 1) * 16 + (slot & 1) * 8 + (lane >> 2);
        const float S  = redS[row * 4 + 0] + redS[row * 4 + 1]
                       + redS[row * 4 + 2] + redS[row * 4 + 3];
        const float Q  = redS2[row * 4 + 0] + redS2[row * 4 + 1]
                       + redS2[row * 4 + 2] + redS2[row * 4 + 3];
        const float mean = S * (1.0f / D);
        const float var  = fmaxf(Q * (1.0f / D) - mean * mean, 0.f);
        const float rstd = rsqrtf(var + LN_EPS);
        const int gr = m0 + row;
        if (gr < n) {
            const int t = slot >> 1, h = slot & 1;
#pragma unroll
            for (int j = 0; j < 8; j++) {
                const int col = wn * 64 + j * 8 + (lane & 3) * 2;
                float2 o;
                o.x = (acc[t][j][h * 2 + 0] - mean) * rstd * gam_s[col]     + bet_s[col];
                o.y = (acc[t][j][h * 2 + 1] - mean) * rstd * gam_s[col + 1] + bet_s[col + 1];
                *(float2*)&out[(size_t)gr * D + col] = o;
            }
        }
    }
}

// ---------------------------------------------------------------------------
extern "C" void kernel_launch(void* const* d_in, const int* in_sizes, int n_in,
                              void* d_out, int out_size)
{
    const float* feats = (const float*)d_in[0];
    const int*   nbrs  = (const int*)d_in[1];
    const float* iw    = (const float*)d_in[2];
    const float* Wm    = (const float*)d_in[3];
    const float* bias  = (const float*)d_in[4];
    const float* gam   = (const float*)d_in[5];
    const float* bet   = (const float*)d_in[6];
    float*       out   = (float*)d_out;

    const int n = in_sizes[0] / D;   // 50000

    cudaFuncSetAttribute(gemm_ln_mma_kernel,
                         cudaFuncAttributeMaxDynamicSharedMemorySize, SMEM_TOTAL);

    prep_w_kernel<<<dim3(8, 8), dim3(32, 8)>>>(Wm);
    const int total4 = n * (D / 4);
    feat_half_kernel<<<(total4 + 255) / 256, 256>>>(feats, total4);
    gather_kernel<<<(n + 3) / 4, 256>>>(nbrs, iw, n);
    gemm_ln_mma_kernel<<<(n + TILE_M - 1) / TILE_M, 256, SMEM_TOTAL>>>(bias, gam, bet, out, n);
}

// round 10
// speedup vs baseline: 3.6325x; 1.1690x over previous
#include <cuda_runtime.h>
#include <cuda_fp16.h>
#include <cstdint>

#define D       256
#define KNBR    16
#define MAXN    50000
#define LN_EPS  1e-5f
#define TILE_M  64
#define KCH     64
#define ROWP    72      // padded row pitch in fp16 elems (144 B) -> conflict-free ldmatrix

// ---------------- scratch (static device arrays; no allocations) ------------
__device__ __half feat16[(size_t)MAXN * D];   // fp16 features (25.6 MB)
__device__ __half g_half[(size_t)MAXN * D];   // aggregated g, fp16 (25.6 MB)
__device__ __half wt16[D * D];                // [n][k] = W[k][n] fp16

// ---------------- smem layout for GEMM (bytes) ------------------------------
#define A_BYTES  (TILE_M * ROWP * 2)               //  9216
#define B_BYTES  (D * ROWP * 2)                    // 36864
#define OFF_A    0
#define OFF_B    (A_BYTES)
#define STAGE    (A_BYTES + B_BYTES)               // 46080
#define OFF_PAR  (2 * STAGE)                       // 92160 : bias|gamma|beta
#define OFF_REDS (OFF_PAR + 3 * D * 4)             // 95232
#define OFF_RED2 (OFF_REDS + TILE_M * 4 * 4)       // 96256
#define SMEM_TOTAL (OFF_RED2 + TILE_M * 4 * 4)     // 97280  -> 2 CTAs/SM

// ---------------- helpers ---------------------------------------------------
__device__ __forceinline__ uint32_t smem_u32(const void* p) {
    uint32_t a;
    asm("{ .reg .u64 t; cvta.to.shared.u64 t, %1; cvt.u32.u64 %0, t; }"
        : "=r"(a) : "l"(p));
    return a;
}
__device__ __forceinline__ void cp16(uint32_t dst, const void* src, bool valid) {
    const int sz = valid ? 16 : 0;
    asm volatile("cp.async.cg.shared.global [%0], [%1], 16, %2;"
                 :: "r"(dst), "l"(src), "r"(sz));
}
__device__ __forceinline__ void ldm4(uint32_t* r, uint32_t addr) {
    asm volatile("ldmatrix.sync.aligned.m8n8.x4.shared.b16 {%0,%1,%2,%3}, [%4];"
                 : "=r"(r[0]), "=r"(r[1]), "=r"(r[2]), "=r"(r[3]) : "r"(addr));
}
__device__ __forceinline__ void mma_f16(float* c, const uint32_t* a,
                                        uint32_t b0, uint32_t b1) {
    asm volatile("mma.sync.aligned.m16n8k16.row.col.f32.f16.f16.f32 "
                 "{%0,%1,%2,%3}, {%4,%5,%6,%7}, {%8,%9}, {%0,%1,%2,%3};"
                 : "+f"(c[0]), "+f"(c[1]), "+f"(c[2]), "+f"(c[3])
                 : "r"(a[0]), "r"(a[1]), "r"(a[2]), "r"(a[3]), "r"(b0), "r"(b1));
}

// ---------------------------------------------------------------------------
// Kernel 0 (merged): blocks [0, nblk_feat) convert features fp32 -> fp16;
// blocks [nblk_feat, nblk_feat+64) transpose W -> fp16 [n][k] via smem tile.
// ---------------------------------------------------------------------------
__global__ __launch_bounds__(256) void prep_kernel(
    const float* __restrict__ feats,
    const float* __restrict__ W,
    int total4, int nblk_feat)
{
    __shared__ float s[32][33];
    const int b   = blockIdx.x;
    const int tid = threadIdx.x;

    if (b < nblk_feat) {
        const int i = b * 256 + tid;
        if (i >= total4) return;
        const float4 v = ((const float4*)feats)[i];
        const __half2 a = __floats2half2_rn(v.x, v.y);
        const __half2 c = __floats2half2_rn(v.z, v.w);
        uint2 pk;
        pk.x = *(const uint32_t*)&a;
        pk.y = *(const uint32_t*)&c;
        *(uint2*)&feat16[(size_t)i * 4] = pk;
    } else {
        const int bb = b - nblk_feat;             // 0..63
        const int n0 = (bb & 7) * 32, k0 = (bb >> 3) * 32;
        const int tx = tid & 31, ty = tid >> 5;   // 32 x 8
#pragma unroll
        for (int i = 0; i < 4; i++)
            s[ty + 8 * i][tx] = W[(size_t)(k0 + ty + 8 * i) * D + n0 + tx];
        __syncthreads();
#pragma unroll
        for (int i = 0; i < 4; i++) {
            const int nl = ty + 8 * i;
            wt16[(size_t)(n0 + nl) * D + k0 + tx] = __float2half_rn(s[tx][nl]);
        }
    }
}

// ---------------------------------------------------------------------------
// Kernel A: warp-per-node gather.  Lane l reads 8 halves (uint4) of each
// neighbor row; weights/indices staged in lanes 0..15 and broadcast via
// shuffles.  No shared memory, no barriers.  8 nodes per 256-thread block.
// ---------------------------------------------------------------------------
__global__ __launch_bounds__(256) void gather_kernel(
    const int* __restrict__ nbrs,
    const float* __restrict__ iw,
    int n)
{
    const int lane = threadIdx.x & 31;
    const int node = blockIdx.x * 8 + (threadIdx.x >> 5);
    if (node >= n) return;   // warp-uniform

    float w = 0.f;
    int   ix = 0;
    if (lane < KNBR) {
        w  = iw[(size_t)node * KNBR + lane];
        ix = nbrs[(size_t)node * KNBR + lane];
        ix = ix < 0 ? 0 : (ix >= n ? n - 1 : ix);
    }
    // total weight (lanes >= 16 contribute 0)
    float wsum = w;
#pragma unroll
    for (int o = 16; o; o >>= 1) wsum += __shfl_xor_sync(0xffffffffu, wsum, o);
    const bool zero = (wsum == 0.f);
    const float inv = zero ? 0.f : 1.0f / wsum;

    const uint4* fp = (const uint4*)feat16;      // 8 halves per load
    float acc[8];
#pragma unroll
    for (int j = 0; j < 8; j++) acc[j] = 0.f;

#pragma unroll
    for (int k = 0; k < KNBR; k++) {
        const float wr = __shfl_sync(0xffffffffu, w,  k);
        const int   ir = __shfl_sync(0xffffffffu, ix, k);
        const float wk = zero ? (1.0f / KNBR) : wr * inv;
        const uint4 raw = fp[(size_t)ir * (D / 8) + lane];
        const __half2* h = (const __half2*)&raw;
#pragma unroll
        for (int j = 0; j < 4; j++) {
            const float2 f = __half22float2(h[j]);
            acc[2 * j]     = fmaf(wk, f.x, acc[2 * j]);
            acc[2 * j + 1] = fmaf(wk, f.y, acc[2 * j + 1]);
        }
    }

    uint4 o;
    {
        const __half2 p0 = __floats2half2_rn(acc[0], acc[1]);
        const __half2 p1 = __floats2half2_rn(acc[2], acc[3]);
        const __half2 p2 = __floats2half2_rn(acc[4], acc[5]);
        const __half2 p3 = __floats2half2_rn(acc[6], acc[7]);
        o.x = *(const uint32_t*)&p0;
        o.y = *(const uint32_t*)&p1;
        o.z = *(const uint32_t*)&p2;
        o.w = *(const uint32_t*)&p3;
    }
    *(uint4*)&g_half[(size_t)node * D + lane * 8] = o;
}

// ---------------------------------------------------------------------------
// Kernel B: fp16 GEMM via mma.sync (m16n8k16), single pass,
// tile 64x256, K in 4 chunks of 64, cp.async double-buffering, fused LN.
// 2 CTAs/SM (97 KB smem, regs capped at 128).  [proven R8 version]
// ---------------------------------------------------------------------------
__global__ __launch_bounds__(256, 2) void gemm_ln_mma_kernel(
    const float* __restrict__ bias,
    const float* __restrict__ gamma,
    const float* __restrict__ beta,
    float* __restrict__ out, int n)
{
    extern __shared__ char smem[];
    const uint32_t sb = smem_u32(smem);
    const int tid  = threadIdx.x;
    const int lane = tid & 31;
    const int wid  = tid >> 5;
    const int wm   = wid & 1;
    const int wn   = wid >> 1;
    const int m0   = blockIdx.x * TILE_M;

    {
        float* p = (float*)(smem + OFF_PAR);
        for (int i = tid; i < D; i += 256) {
            p[i]         = bias[i];
            p[D + i]     = gamma[i];
            p[2 * D + i] = beta[i];
        }
    }

    float acc[2][8][4];
#pragma unroll
    for (int t = 0; t < 2; t++)
#pragma unroll
        for (int j = 0; j < 8; j++)
#pragma unroll
            for (int q = 0; q < 4; q++) acc[t][j][q] = 0.f;

    const uint32_t a_lane = (uint32_t)(lane & 15) * (ROWP * 2) + (uint32_t)(lane >> 4) * 16;
    const uint32_t b_lane = (uint32_t)((lane & 7) + ((lane >> 4) << 3)) * (ROWP * 2)
                          + (uint32_t)((lane >> 3) & 1) * 16;

    auto load_stage = [&](int st, int c) {
        const int k0 = c * KCH;
        const uint32_t base = sb + st * STAGE;
#pragma unroll
        for (int i = 0; i < 2; i++) {
            const int idx = tid + i * 256;
            const int r  = idx >> 3;
            const int c8 = idx & 7;
            const int grow = m0 + r;
            const bool valid = grow < n;
            const int gr = valid ? grow : 0;
            const __half* src = g_half + (size_t)gr * D + k0 + c8 * 8;
            cp16(base + OFF_A + (uint32_t)r * (ROWP * 2) + (uint32_t)c8 * 16, src, valid);
        }
#pragma unroll
        for (int i = 0; i < 8; i++) {
            const int idx = tid + i * 256;
            const int r  = idx >> 3;
            const int c8 = idx & 7;
            const __half* src = wt16 + (size_t)r * D + k0 + c8 * 8;
            cp16(base + OFF_B + (uint32_t)r * (ROWP * 2) + (uint32_t)c8 * 16, src, true);
        }
        asm volatile("cp.async.commit_group;");
    };

    load_stage(0, 0);

#pragma unroll
    for (int c = 0; c < 4; c++) {
        if (c < 3) {
            load_stage((c + 1) & 1, c + 1);
            asm volatile("cp.async.wait_group 1;");
        } else {
            asm volatile("cp.async.wait_group 0;");
        }
        __syncthreads();

        const uint32_t base = sb + (uint32_t)(c & 1) * STAGE;
#pragma unroll
        for (int ks = 0; ks < 4; ks++) {
            uint32_t ah[2][4], bh[4][4];
#pragma unroll
            for (int t = 0; t < 2; t++) {
                const uint32_t ao = base + OFF_A
                                  + (uint32_t)(wm * 32 + t * 16) * (ROWP * 2)
                                  + (uint32_t)ks * 32 + a_lane;
                ldm4(ah[t], ao);
            }
#pragma unroll
            for (int p = 0; p < 4; p++) {
                const uint32_t bo = base + OFF_B
                                  + (uint32_t)(wn * 64 + p * 16) * (ROWP * 2)
                                  + (uint32_t)ks * 32 + b_lane;
                ldm4(bh[p], bo);
            }
#pragma unroll
            for (int t = 0; t < 2; t++)
#pragma unroll
                for (int j = 0; j < 8; j++)
                    mma_f16(acc[t][j], ah[t],
                            bh[j >> 1][(j & 1) * 2], bh[j >> 1][(j & 1) * 2 + 1]);
        }
        __syncthreads();
    }

    // ---------------- fused LayerNorm epilogue -----------------------------
    const float* bias_s = (const float*)(smem + OFF_PAR);
    const float* gam_s  = bias_s + D;
    const float* bet_s  = bias_s + 2 * D;

    float s[4]  = {0.f, 0.f, 0.f, 0.f};
    float s2[4] = {0.f, 0.f, 0.f, 0.f};
#pragma unroll
    for (int t = 0; t < 2; t++)
#pragma unroll
        for (int j = 0; j < 8; j++)
#pragma unroll
            for (int q = 0; q < 4; q++) {
                const int col = wn * 64 + j * 8 + (lane & 3) * 2 + (q & 1);
                const float v = acc[t][j][q] + bias_s[col];
                acc[t][j][q] = v;
                const int slot = t * 2 + (q >> 1);
                s[slot] += v;
                s2[slot] = fmaf(v, v, s2[slot]);
            }
#pragma unroll
    for (int slot = 0; slot < 4; slot++) {
        s[slot]  += __shfl_xor_sync(0xffffffffu, s[slot], 1);
        s2[slot] += __shfl_xor_sync(0xffffffffu, s2[slot], 1);
        s[slot]  += __shfl_xor_sync(0xffffffffu, s[slot], 2);
        s2[slot] += __shfl_xor_sync(0xffffffffu, s2[slot], 2);
    }
    float* redS  = (float*)(smem + OFF_REDS);
    float* redS2 = (float*)(smem + OFF_RED2);
    if ((lane & 3) == 0) {
#pragma unroll
        for (int slot = 0; slot < 4; slot++) {
            const int row = wm * 32 + (slot >> 1) * 16 + (slot & 1) * 8 + (lane >> 2);
            redS[row * 4 + wn]  = s[slot];
            redS2[row * 4 + wn] = s2[slot];
        }
    }
    __syncthreads();

#pragma unroll
    for (int slot = 0; slot < 4; slot++) {
        const int row = wm * 32 + (slot >> 1) * 16 + (slot & 1) * 8 + (lane >> 2);
        const float S  = redS[row * 4 + 0] + redS[row * 4 + 1]
                       + redS[row * 4 + 2] + redS[row * 4 + 3];
        const float Q  = redS2[row * 4 + 0] + redS2[row * 4 + 1]
                       + redS2[row * 4 + 2] + redS2[row * 4 + 3];
        const float mean = S * (1.0f / D);
        const float var  = fmaxf(Q * (1.0f / D) - mean * mean, 0.f);
        const float rstd = rsqrtf(var + LN_EPS);
        const int gr = m0 + row;
        if (gr < n) {
            const int t = slot >> 1, h = slot & 1;
#pragma unroll
            for (int j = 0; j < 8; j++) {
                const int col = wn * 64 + j * 8 + (lane & 3) * 2;
                float2 o;
                o.x = (acc[t][j][h * 2 + 0] - mean) * rstd * gam_s[col]     + bet_s[col];
                o.y = (acc[t][j][h * 2 + 1] - mean) * rstd * gam_s[col + 1] + bet_s[col + 1];
                *(float2*)&out[(size_t)gr * D + col] = o;
            }
        }
    }
}

// ---------------------------------------------------------------------------
extern "C" void kernel_launch(void* const* d_in, const int* in_sizes, int n_in,
                              void* d_out, int out_size)
{
    const float* feats = (const float*)d_in[0];
    const int*   nbrs  = (const int*)d_in[1];
    const float* iw    = (const float*)d_in[2];
    const float* Wm    = (const float*)d_in[3];
    const float* bias  = (const float*)d_in[4];
    const float* gam   = (const float*)d_in[5];
    const float* bet   = (const float*)d_in[6];
    float*       out   = (float*)d_out;

    const int n = in_sizes[0] / D;   // 50000

    cudaFuncSetAttribute(gemm_ln_mma_kernel,
                         cudaFuncAttributeMaxDynamicSharedMemorySize, SMEM_TOTAL);

    const int total4    = n * (D / 4);
    const int nblk_feat = (total4 + 255) / 256;
    prep_kernel<<<nblk_feat + 64, 256>>>(feats, Wm, total4, nblk_feat);
    gather_kernel<<<(n + 7) / 8, 256>>>(nbrs, iw, n);
    gemm_ln_mma_kernel<<<(n + TILE_M - 1) / TILE_M, 256, SMEM_TOTAL>>>(bias, gam, bet, out, n);
}